// round 2
// baseline (speedup 1.0000x reference)
#include <cuda_runtime.h>
#include <math.h>

// ---------------------------------------------------------------------------
// WITT AdaLN Swin block, fp32 baseline.
// B=16, H=W=64, C=256, NH=8, HD=32, WS=8, SS=4, N=64 tokens/window,
// NWIN=64 windows/image, MLP_H=1024. Tokens T = 65536.
//
// Input order (metadata):
//  0 x[16,4096,256] 1 cond[16,256] 2 norm1_g 3 norm1_b 4 w_qkv[256,768]
//  5 b_qkv[768] 6 rel_bias[225,8] 7 w_proj[256,256] 8 b_proj[256]
//  9 norm2_g 10 norm2_b 11 w_fc1[256,1024] 12 b_fc1[1024]
// 13 w_fc2[1024,256] 14 b_fc2[256] 15 w_ada[256,1536] 16 b_ada[1536]
// ---------------------------------------------------------------------------

#define TOK 65536

// Scratch (static device globals; allocation-free rule)
__device__ __align__(16) float g_ada [16 * 1536];
__device__ __align__(16) float g_hwin[(size_t)TOK * 256];   // LN1+mod, window order
__device__ __align__(16) float g_qkv [(size_t)TOK * 768];
__device__ __align__(16) float g_attn[(size_t)TOK * 256];   // attn out, window order
__device__ __align__(16) float g_x1  [(size_t)TOK * 256];   // x after first residual (x-layout)
__device__ __align__(16) float g_h2  [(size_t)TOK * 256];   // LN2+mod
__device__ __align__(16) float g_mlp [(size_t)TOK * 1024];  // GELU(fc1)

// ---------------------------------------------------------------------------
// K0: ada = silu(cond) @ w_ada + b_ada      [16, 1536]
// chunks: sm[0:256] cm[256:512] gm[512:768] sp[768:1024] cp[1024:1280] gp[1280:1536]
// ---------------------------------------------------------------------------
__global__ void ada_kernel(const float* __restrict__ cond,
                           const float* __restrict__ w_ada,
                           const float* __restrict__ b_ada) {
    __shared__ float sc[256];
    int b = blockIdx.x, t = threadIdx.x;
    float v = cond[b * 256 + t];
    sc[t] = v / (1.0f + expf(-v));
    __syncthreads();
    for (int j = t; j < 1536; j += 256) {
        float acc = b_ada[j];
        #pragma unroll 4
        for (int i = 0; i < 256; i++) acc = fmaf(sc[i], __ldg(&w_ada[i * 1536 + j]), acc);
        g_ada[b * 1536 + j] = acc;
    }
}

// ---------------------------------------------------------------------------
// K1/K5: LayerNorm + AdaLN modulation. PASS 0 also does cyclic shift (-4,-4)
// and window partition (writes window-ordered g_hwin). PASS 1 is plain layout
// (reads g_x1, writes g_h2).
// One warp per token, 8 channels per lane.
// ---------------------------------------------------------------------------
template <int PASS>
__global__ void ln_mod_kernel(const float* __restrict__ xin,
                              const float* __restrict__ gamma,
                              const float* __restrict__ beta) {
    int gw   = (blockIdx.x * blockDim.x + threadIdx.x) >> 5;  // token index (output order)
    int lane = threadIdx.x & 31;
    int b = gw >> 12;

    const float* src;
    float* dst;
    if (PASS == 0) {
        int t = gw & 63, widx = gw >> 6;
        int wh = (widx >> 3) & 7, ww = widx & 7;
        int r = t >> 3, c = t & 7;
        int sr = (wh * 8 + r + 4) & 63;     // roll(-4): shifted row -> source row
        int sc2 = (ww * 8 + c + 4) & 63;
        src = xin + ((size_t)(b * 4096 + sr * 64 + sc2)) * 256;
        dst = g_hwin + (size_t)gw * 256;
    } else {
        src = g_x1 + (size_t)gw * 256;
        dst = g_h2 + (size_t)gw * 256;
    }

    float4 v0 = *(const float4*)(src + lane * 8);
    float4 v1 = *(const float4*)(src + lane * 8 + 4);
    float e[8] = {v0.x, v0.y, v0.z, v0.w, v1.x, v1.y, v1.z, v1.w};

    float s = 0.f, q = 0.f;
    #pragma unroll
    for (int j = 0; j < 8; j++) { s += e[j]; q += e[j] * e[j]; }
    #pragma unroll
    for (int off = 16; off > 0; off >>= 1) {
        s += __shfl_xor_sync(0xffffffffu, s, off);
        q += __shfl_xor_sync(0xffffffffu, q, off);
    }
    float mean = s * (1.0f / 256.0f);
    float var  = q * (1.0f / 256.0f) - mean * mean;
    float rstd = rsqrtf(var + 1e-5f);

    const float* scl = g_ada + b * 1536 + (PASS == 0 ? 256 : 1024);  // cm / cp
    const float* sft = g_ada + b * 1536 + (PASS == 0 ? 0   : 768);   // sm / sp

    int ch = lane * 8;
    float o[8];
    #pragma unroll
    for (int j = 0; j < 8; j++) {
        float y = (e[j] - mean) * rstd * __ldg(&gamma[ch + j]) + __ldg(&beta[ch + j]);
        o[j] = y * (1.0f + scl[ch + j]) + sft[ch + j];
    }
    *(float4*)(dst + ch)     = make_float4(o[0], o[1], o[2], o[3]);
    *(float4*)(dst + ch + 4) = make_float4(o[4], o[5], o[6], o[7]);
}

// ---------------------------------------------------------------------------
// K3: attention per (window, head). 64 threads = one query row each.
// S = (q/sqrt(32)) k^T + rel_bias + shift_mask ; softmax ; O = P v
// qkv cols: q = h*32+d, k = 256+h*32+d, v = 512+h*32+d
// ---------------------------------------------------------------------------
__global__ void attn_kernel(const float* __restrict__ rel_bias) {
    __shared__ float ks[64][33];
    __shared__ float vs[64][33];
    int widx = blockIdx.x;          // 0..1023
    int h    = blockIdx.y;          // 0..7
    int n    = threadIdx.x;         // 0..63

    const float* base = g_qkv + (size_t)widx * 64 * 768;
    const float* rowp = base + (size_t)n * 768 + h * 32;

    #pragma unroll
    for (int j = 0; j < 8; j++) {
        float4 kk = *(const float4*)(rowp + 256 + j * 4);
        ks[n][j * 4 + 0] = kk.x; ks[n][j * 4 + 1] = kk.y;
        ks[n][j * 4 + 2] = kk.z; ks[n][j * 4 + 3] = kk.w;
        float4 vv = *(const float4*)(rowp + 512 + j * 4);
        vs[n][j * 4 + 0] = vv.x; vs[n][j * 4 + 1] = vv.y;
        vs[n][j * 4 + 2] = vv.z; vs[n][j * 4 + 3] = vv.w;
    }
    const float scale = 0.17677669529663687f;  // 32^-0.5
    float q[32];
    #pragma unroll
    for (int j = 0; j < 8; j++) {
        float4 qq = *(const float4*)(rowp + j * 4);
        q[j * 4 + 0] = qq.x * scale; q[j * 4 + 1] = qq.y * scale;
        q[j * 4 + 2] = qq.z * scale; q[j * 4 + 3] = qq.w * scale;
    }
    __syncthreads();

    int wh = (widx >> 3) & 7, ww = widx & 7;
    int i1 = n >> 3, j1 = n & 7;
    int rv = wh * 8 + i1, cv = ww * 8 + j1;
    int idn = (rv < 56 ? 0 : (rv < 60 ? 1 : 2)) * 3 + (cv < 56 ? 0 : (cv < 60 ? 1 : 2));

    float p[64];
    float mx = -1e30f;
    #pragma unroll
    for (int m = 0; m < 64; m++) {
        float s = 0.f;
        #pragma unroll
        for (int d = 0; d < 32; d++) s = fmaf(q[d], ks[m][d], s);
        int i2 = m >> 3, j2 = m & 7;
        s += __ldg(&rel_bias[((i1 - i2 + 7) * 15 + (j1 - j2 + 7)) * 8 + h]);
        int rv2 = wh * 8 + i2, cv2 = ww * 8 + j2;
        int idm = (rv2 < 56 ? 0 : (rv2 < 60 ? 1 : 2)) * 3 +
                  (cv2 < 56 ? 0 : (cv2 < 60 ? 1 : 2));
        if (idm != idn) s -= 100.0f;
        p[m] = s;
        mx = fmaxf(mx, s);
    }
    float sum = 0.f;
    #pragma unroll
    for (int m = 0; m < 64; m++) { p[m] = __expf(p[m] - mx); sum += p[m]; }
    float inv = 1.0f / sum;

    float* outp = g_attn + (size_t)(widx * 64 + n) * 256 + h * 32;
    #pragma unroll
    for (int d0 = 0; d0 < 32; d0 += 4) {
        float o0 = 0.f, o1 = 0.f, o2 = 0.f, o3 = 0.f;
        #pragma unroll
        for (int m = 0; m < 64; m++) {
            float pm = p[m];
            o0 = fmaf(pm, vs[m][d0 + 0], o0);
            o1 = fmaf(pm, vs[m][d0 + 1], o1);
            o2 = fmaf(pm, vs[m][d0 + 2], o2);
            o3 = fmaf(pm, vs[m][d0 + 3], o3);
        }
        *(float4*)(outp + d0) = make_float4(o0 * inv, o1 * inv, o2 * inv, o3 * inv);
    }
}

// ---------------------------------------------------------------------------
// Tiled SGEMM, 128x128x16 tile, 256 threads, 8x8 per thread. M=65536.
// MODE 0: g_qkv  = g_hwin @ w_qkv + b_qkv                       (N=768,K=256)
// MODE 1: g_x1[perm] = x[perm] + gm * (g_attn @ w_proj + b)     (N=256,K=256)
// MODE 2: g_mlp  = gelu(g_h2 @ w_fc1 + b_fc1)                   (N=1024,K=256)
// MODE 3: d_out  = g_x1 + gp * (g_mlp @ w_fc2 + b_fc2)          (N=256,K=1024)
// ---------------------------------------------------------------------------
template <int MODE>
__global__ void sgemm_kernel(const float* __restrict__ W,
                             const float* __restrict__ bias,
                             const float* __restrict__ xres,
                             float* __restrict__ outp) {
    constexpr int K = (MODE == 3) ? 1024 : 256;
    constexpr int N = (MODE == 0) ? 768 : (MODE == 2) ? 1024 : 256;
    const float* A = (MODE == 0) ? g_hwin : (MODE == 1) ? g_attn
                   : (MODE == 2) ? g_h2   : g_mlp;

    __shared__ float As[16][132];
    __shared__ float Bs[16][132];

    int tid = threadIdx.x;
    int bm = blockIdx.y * 128, bn = blockIdx.x * 128;

    float acc[8][8];
    #pragma unroll
    for (int i = 0; i < 8; i++)
        #pragma unroll
        for (int j = 0; j < 8; j++) acc[i][j] = 0.f;

    int arow = tid >> 2, acol = (tid & 3) * 4;
    int brow = tid >> 5, bcol = (tid & 31) * 4;
    int tm = (tid >> 4) * 8, tn = (tid & 15) * 8;
    const float* Abase = A + (size_t)bm * K;

    for (int k0 = 0; k0 < K; k0 += 16) {
        #pragma unroll
        for (int i = 0; i < 2; i++) {
            int r = arow + i * 64;
            float4 a = *(const float4*)(Abase + (size_t)r * K + k0 + acol);
            As[acol + 0][r] = a.x; As[acol + 1][r] = a.y;
            As[acol + 2][r] = a.z; As[acol + 3][r] = a.w;
        }
        #pragma unroll
        for (int i = 0; i < 2; i++) {
            int r = brow + i * 8;
            *(float4*)&Bs[r][bcol] = __ldg((const float4*)(W + (size_t)(k0 + r) * N + bn + bcol));
        }
        __syncthreads();
        #pragma unroll
        for (int k = 0; k < 16; k++) {
            float ra[8], rb[8];
            *(float4*)(ra)     = *(const float4*)&As[k][tm];
            *(float4*)(ra + 4) = *(const float4*)&As[k][tm + 4];
            *(float4*)(rb)     = *(const float4*)&Bs[k][tn];
            *(float4*)(rb + 4) = *(const float4*)&Bs[k][tn + 4];
            #pragma unroll
            for (int i = 0; i < 8; i++)
                #pragma unroll
                for (int j = 0; j < 8; j++)
                    acc[i][j] = fmaf(ra[i], rb[j], acc[i][j]);
        }
        __syncthreads();
    }

    #pragma unroll
    for (int i = 0; i < 8; i++) {
        int row = bm + tm + i;
        int col = bn + tn;
        if (MODE == 0) {
            float o[8];
            #pragma unroll
            for (int j = 0; j < 8; j++) o[j] = acc[i][j] + __ldg(&bias[col + j]);
            float* d = g_qkv + (size_t)row * 768 + col;
            *(float4*)(d)     = make_float4(o[0], o[1], o[2], o[3]);
            *(float4*)(d + 4) = make_float4(o[4], o[5], o[6], o[7]);
        } else if (MODE == 1) {
            // window-reverse + roll(+4) + residual + gm gate
            int b = row >> 12, t = row & 63, widx = row >> 6;
            int wh = (widx >> 3) & 7, ww = widx & 7;
            int r2 = t >> 3, c2 = t & 7;
            int pr = (wh * 8 + r2 + 4) & 63;
            int pc = (ww * 8 + c2 + 4) & 63;
            size_t prow = (size_t)(b * 4096 + pr * 64 + pc);
            const float* gm = g_ada + b * 1536 + 512;
            float o[8];
            #pragma unroll
            for (int j = 0; j < 8; j++) {
                float val = acc[i][j] + __ldg(&bias[col + j]);
                o[j] = __ldg(&xres[prow * 256 + col + j]) + gm[col + j] * val;
            }
            float* d = g_x1 + prow * 256 + col;
            *(float4*)(d)     = make_float4(o[0], o[1], o[2], o[3]);
            *(float4*)(d + 4) = make_float4(o[4], o[5], o[6], o[7]);
        } else if (MODE == 2) {
            float o[8];
            #pragma unroll
            for (int j = 0; j < 8; j++) {
                float v = acc[i][j] + __ldg(&bias[col + j]);
                o[j] = 0.5f * v * (1.0f + erff(v * 0.70710678118654752f));
            }
            float* d = g_mlp + (size_t)row * 1024 + col;
            *(float4*)(d)     = make_float4(o[0], o[1], o[2], o[3]);
            *(float4*)(d + 4) = make_float4(o[4], o[5], o[6], o[7]);
        } else {
            int b = row >> 12;
            const float* gp = g_ada + b * 1536 + 1280;
            const float* x1 = g_x1 + (size_t)row * 256 + col;
            float o[8];
            #pragma unroll
            for (int j = 0; j < 8; j++) {
                float v = acc[i][j] + __ldg(&bias[col + j]);
                o[j] = x1[j] + gp[col + j] * v;
            }
            float* d = outp + (size_t)row * 256 + col;
            *(float4*)(d)     = make_float4(o[0], o[1], o[2], o[3]);
            *(float4*)(d + 4) = make_float4(o[4], o[5], o[6], o[7]);
        }
    }
}

// ---------------------------------------------------------------------------
extern "C" void kernel_launch(void* const* d_in, const int* in_sizes, int n_in,
                              void* d_out, int out_size) {
    const float* x       = (const float*)d_in[0];
    const float* cond    = (const float*)d_in[1];
    const float* norm1_g = (const float*)d_in[2];
    const float* norm1_b = (const float*)d_in[3];
    const float* w_qkv   = (const float*)d_in[4];
    const float* b_qkv   = (const float*)d_in[5];
    const float* rel_b   = (const float*)d_in[6];
    const float* w_proj  = (const float*)d_in[7];
    const float* b_proj  = (const float*)d_in[8];
    const float* norm2_g = (const float*)d_in[9];
    const float* norm2_b = (const float*)d_in[10];
    const float* w_fc1   = (const float*)d_in[11];
    const float* b_fc1   = (const float*)d_in[12];
    const float* w_fc2   = (const float*)d_in[13];
    const float* b_fc2   = (const float*)d_in[14];
    const float* w_ada   = (const float*)d_in[15];
    const float* b_ada   = (const float*)d_in[16];
    float* out = (float*)d_out;

    ada_kernel<<<16, 256>>>(cond, w_ada, b_ada);
    ln_mod_kernel<0><<<8192, 256>>>(x, norm1_g, norm1_b);
    sgemm_kernel<0><<<dim3(6, 512), 256>>>(w_qkv, b_qkv, nullptr, nullptr);
    attn_kernel<<<dim3(1024, 8), 64>>>(rel_b);
    sgemm_kernel<1><<<dim3(2, 512), 256>>>(w_proj, b_proj, x, nullptr);
    ln_mod_kernel<1><<<8192, 256>>>(x, norm2_g, norm2_b);
    sgemm_kernel<2><<<dim3(8, 512), 256>>>(w_fc1, b_fc1, nullptr, nullptr);
    sgemm_kernel<3><<<dim3(2, 512), 256>>>(w_fc2, b_fc2, nullptr, out);
}

// round 3
// speedup vs baseline: 1.4682x; 1.4682x over previous
#include <cuda_runtime.h>
#include <cuda_bf16.h>
#include <mma.h>
#include <math.h>

using namespace nvcuda;

// ---------------------------------------------------------------------------
// WITT AdaLN Swin block. bf16 tensor-core GEMMs + fused attention.
// B=16, H=W=64, C=256, NH=8, HD=32, WS=8, SS=4, N=64, NWIN=64, MLP_H=1024.
// TOK = 65536 tokens.
// ---------------------------------------------------------------------------

#define TOK 65536

__device__ __align__(16) float g_ada [16 * 1536];
__device__ __align__(16) float g_hwin[(size_t)TOK * 256];   // LN1+mod, window order
__device__ __align__(16) float g_qkv [(size_t)TOK * 768];   // qkv (+bias), window order
__device__ __align__(16) float g_attn[(size_t)TOK * 256];   // attn out, window order
__device__ __align__(16) float g_tmp [(size_t)TOK * 256];   // raw GEMM out (proj / fc2)
__device__ __align__(16) float g_x1  [(size_t)TOK * 256];   // x after 1st residual (x-order)
__device__ __align__(16) float g_h2  [(size_t)TOK * 256];   // LN2+mod
__device__ __align__(16) float g_mlp [(size_t)TOK * 1024];  // GELU(fc1)

// ---------------------------------------------------------------------------
// ada = silu(cond) @ w_ada + b_ada   [16,1536]
// chunks: sm 0 | cm 256 | gm 512 | sp 768 | cp 1024 | gp 1280
// ---------------------------------------------------------------------------
__global__ void ada_kernel(const float* __restrict__ cond,
                           const float* __restrict__ w_ada,
                           const float* __restrict__ b_ada) {
    __shared__ float sc[256];
    int b = blockIdx.x, t = threadIdx.x;
    float v = cond[b * 256 + t];
    sc[t] = v / (1.0f + expf(-v));
    __syncthreads();
    for (int j = t; j < 1536; j += 256) {
        float acc = b_ada[j];
        #pragma unroll 4
        for (int i = 0; i < 256; i++) acc = fmaf(sc[i], __ldg(&w_ada[i * 1536 + j]), acc);
        g_ada[b * 1536 + j] = acc;
    }
}

// ---------------------------------------------------------------------------
// LayerNorm + AdaLN modulation. PASS 0: roll(-4,-4) + window partition from x.
// PASS 1: plain (g_x1 -> g_h2). One warp per token.
// ---------------------------------------------------------------------------
template <int PASS>
__global__ void ln_mod_kernel(const float* __restrict__ xin,
                              const float* __restrict__ gamma,
                              const float* __restrict__ beta) {
    int gw   = (blockIdx.x * blockDim.x + threadIdx.x) >> 5;
    int lane = threadIdx.x & 31;
    int b = gw >> 12;

    const float* src;
    float* dst;
    if (PASS == 0) {
        int t = gw & 63, widx = (gw >> 6) & 63;
        int wh = (widx >> 3) & 7, ww = widx & 7;
        int r = t >> 3, c = t & 7;
        int sr  = (wh * 8 + r + 4) & 63;
        int sc2 = (ww * 8 + c + 4) & 63;
        src = xin + ((size_t)(b * 4096 + sr * 64 + sc2)) * 256;
        dst = g_hwin + (size_t)gw * 256;
    } else {
        src = g_x1 + (size_t)gw * 256;
        dst = g_h2 + (size_t)gw * 256;
    }

    float4 v0 = *(const float4*)(src + lane * 8);
    float4 v1 = *(const float4*)(src + lane * 8 + 4);
    float e[8] = {v0.x, v0.y, v0.z, v0.w, v1.x, v1.y, v1.z, v1.w};

    float s = 0.f, q = 0.f;
    #pragma unroll
    for (int j = 0; j < 8; j++) { s += e[j]; q += e[j] * e[j]; }
    #pragma unroll
    for (int off = 16; off > 0; off >>= 1) {
        s += __shfl_xor_sync(0xffffffffu, s, off);
        q += __shfl_xor_sync(0xffffffffu, q, off);
    }
    float mean = s * (1.0f / 256.0f);
    float var  = q * (1.0f / 256.0f) - mean * mean;
    float rstd = rsqrtf(var + 1e-5f);

    const float* scl = g_ada + b * 1536 + (PASS == 0 ? 256 : 1024);
    const float* sft = g_ada + b * 1536 + (PASS == 0 ? 0   : 768);

    int ch = lane * 8;
    float o[8];
    #pragma unroll
    for (int j = 0; j < 8; j++) {
        float y = (e[j] - mean) * rstd * __ldg(&gamma[ch + j]) + __ldg(&beta[ch + j]);
        o[j] = y * (1.0f + scl[ch + j]) + sft[ch + j];
    }
    *(float4*)(dst + ch)     = make_float4(o[0], o[1], o[2], o[3]);
    *(float4*)(dst + ch + 4) = make_float4(o[4], o[5], o[6], o[7]);
}

// ---------------------------------------------------------------------------
// Attention per (window, head). 64 threads = one query row each.
// Single-pass unnormalized softmax (logits bounded; no max needed).
// ---------------------------------------------------------------------------
__global__ void attn_kernel(const float* __restrict__ rel_bias) {
    __shared__ float ks[64][33];
    __shared__ float vs[64][33];
    int widx = blockIdx.x;
    int h    = blockIdx.y;
    int n    = threadIdx.x;

    const float* rowp = g_qkv + (size_t)widx * 64 * 768 + (size_t)n * 768 + h * 32;

    #pragma unroll
    for (int j = 0; j < 8; j++) {
        float4 kk = *(const float4*)(rowp + 256 + j * 4);
        ks[n][j * 4 + 0] = kk.x; ks[n][j * 4 + 1] = kk.y;
        ks[n][j * 4 + 2] = kk.z; ks[n][j * 4 + 3] = kk.w;
        float4 vv = *(const float4*)(rowp + 512 + j * 4);
        vs[n][j * 4 + 0] = vv.x; vs[n][j * 4 + 1] = vv.y;
        vs[n][j * 4 + 2] = vv.z; vs[n][j * 4 + 3] = vv.w;
    }
    const float scale = 0.17677669529663687f;
    float q[32];
    #pragma unroll
    for (int j = 0; j < 8; j++) {
        float4 qq = *(const float4*)(rowp + j * 4);
        q[j * 4 + 0] = qq.x * scale; q[j * 4 + 1] = qq.y * scale;
        q[j * 4 + 2] = qq.z * scale; q[j * 4 + 3] = qq.w * scale;
    }
    __syncthreads();

    int wh = (widx >> 3) & 7, ww = widx & 7;
    int i1 = n >> 3, j1 = n & 7;
    int rv = wh * 8 + i1, cv = ww * 8 + j1;
    int idn = (rv < 56 ? 0 : (rv < 60 ? 1 : 2)) * 3 + (cv < 56 ? 0 : (cv < 60 ? 1 : 2));

    float o[32];
    #pragma unroll
    for (int d = 0; d < 32; d++) o[d] = 0.f;
    float sum = 0.f;

    for (int m = 0; m < 64; m++) {
        float s = 0.f;
        #pragma unroll
        for (int d = 0; d < 32; d++) s = fmaf(q[d], ks[m][d], s);
        int i2 = m >> 3, j2 = m & 7;
        s += __ldg(&rel_bias[((i1 - i2 + 7) * 15 + (j1 - j2 + 7)) * 8 + h]);
        int rv2 = wh * 8 + i2, cv2 = ww * 8 + j2;
        int idm = (rv2 < 56 ? 0 : (rv2 < 60 ? 1 : 2)) * 3 +
                  (cv2 < 56 ? 0 : (cv2 < 60 ? 1 : 2));
        if (idm != idn) s -= 100.0f;
        float p = __expf(s);
        sum += p;
        #pragma unroll
        for (int d = 0; d < 32; d++) o[d] = fmaf(p, vs[m][d], o[d]);
    }
    float inv = 1.0f / sum;

    float* outp = g_attn + (size_t)(widx * 64 + n) * 256 + h * 32;
    #pragma unroll
    for (int d = 0; d < 32; d += 4)
        *(float4*)(outp + d) = make_float4(o[d] * inv, o[d+1] * inv, o[d+2] * inv, o[d+3] * inv);
}

// ---------------------------------------------------------------------------
// bf16 tensor-core GEMM (wmma 16x16x16, fp32 accumulate).
// 128x128 block tile, BK=32, 8 warps (4m x 2n), warp tile 32x64.
// Bias folded via accumulator init from replicated-bias smem tile.
// MODE 0: g_qkv = g_hwin @ w_qkv + b           (N=768,K=256)
// MODE 1: g_tmp = g_attn @ w_proj + b          (N=256,K=256)
// MODE 2: g_mlp = gelu(g_h2 @ w_fc1 + b)       (N=1024,K=256)
// MODE 3: g_tmp = g_mlp @ w_fc2 + b            (N=256,K=1024)
// ---------------------------------------------------------------------------
template <int MODE>
__global__ void gemm16_kernel(const float* __restrict__ W,
                              const float* __restrict__ bias,
                              float* __restrict__ Cout) {
    constexpr int K = (MODE == 3) ? 1024 : 256;
    constexpr int N = (MODE == 0) ? 768 : (MODE == 2) ? 1024 : 256;
    const float* A = (MODE == 0) ? g_hwin : (MODE == 1) ? g_attn
                   : (MODE == 2) ? g_h2   : g_mlp;

    __shared__ __nv_bfloat16 As[128][40];
    __shared__ __nv_bfloat16 Bs[32][136];
    __shared__ float biasS[16][136];

    int tid = threadIdx.x;
    int warp = tid >> 5;
    int wm = warp & 3;        // 0..3 -> rows wm*32
    int wn = warp >> 2;       // 0..1 -> cols wn*64
    int bm = blockIdx.y * 128, bn = blockIdx.x * 128;

    for (int i = tid; i < 16 * 128; i += 256)
        biasS[i >> 7][i & 127] = __ldg(&bias[bn + (i & 127)]);
    __syncthreads();

    wmma::fragment<wmma::accumulator, 16, 16, 16, float> acc[2][4];
    #pragma unroll
    for (int mf = 0; mf < 2; mf++)
        #pragma unroll
        for (int nf = 0; nf < 4; nf++)
            wmma::load_matrix_sync(acc[mf][nf], &biasS[0][wn * 64 + nf * 16], 136,
                                   wmma::mem_row_major);

    const float* Abase = A + (size_t)bm * K;

    for (int k0 = 0; k0 < K; k0 += 32) {
        #pragma unroll
        for (int i = tid; i < 1024; i += 256) {          // A: 128x32 = 1024 float4 loads/4
            int r = i >> 3, c4 = (i & 7) * 4;
            float4 a = *(const float4*)(Abase + (size_t)r * K + k0 + c4);
            As[r][c4 + 0] = __float2bfloat16(a.x);
            As[r][c4 + 1] = __float2bfloat16(a.y);
            As[r][c4 + 2] = __float2bfloat16(a.z);
            As[r][c4 + 3] = __float2bfloat16(a.w);
        }
        #pragma unroll
        for (int i = tid; i < 1024; i += 256) {          // B: 32x128
            int r = i >> 5, c4 = (i & 31) * 4;
            float4 b = __ldg((const float4*)(W + (size_t)(k0 + r) * N + bn + c4));
            Bs[r][c4 + 0] = __float2bfloat16(b.x);
            Bs[r][c4 + 1] = __float2bfloat16(b.y);
            Bs[r][c4 + 2] = __float2bfloat16(b.z);
            Bs[r][c4 + 3] = __float2bfloat16(b.w);
        }
        __syncthreads();

        #pragma unroll
        for (int kk = 0; kk < 32; kk += 16) {
            wmma::fragment<wmma::matrix_a, 16, 16, 16, __nv_bfloat16, wmma::row_major> af[2];
            wmma::fragment<wmma::matrix_b, 16, 16, 16, __nv_bfloat16, wmma::row_major> bf[4];
            #pragma unroll
            for (int mf = 0; mf < 2; mf++)
                wmma::load_matrix_sync(af[mf], &As[wm * 32 + mf * 16][kk], 40);
            #pragma unroll
            for (int nf = 0; nf < 4; nf++)
                wmma::load_matrix_sync(bf[nf], &Bs[kk][wn * 64 + nf * 16], 136);
            #pragma unroll
            for (int mf = 0; mf < 2; mf++)
                #pragma unroll
                for (int nf = 0; nf < 4; nf++)
                    wmma::mma_sync(acc[mf][nf], af[mf], bf[nf], acc[mf][nf]);
        }
        __syncthreads();
    }

    if (MODE == 2) {
        #pragma unroll
        for (int mf = 0; mf < 2; mf++)
            #pragma unroll
            for (int nf = 0; nf < 4; nf++)
                #pragma unroll
                for (int i = 0; i < acc[mf][nf].num_elements; i++) {
                    float v = acc[mf][nf].x[i];
                    acc[mf][nf].x[i] = 0.5f * v * (1.0f + erff(v * 0.70710678118654752f));
                }
    }

    #pragma unroll
    for (int mf = 0; mf < 2; mf++)
        #pragma unroll
        for (int nf = 0; nf < 4; nf++)
            wmma::store_matrix_sync(
                Cout + (size_t)(bm + wm * 32 + mf * 16) * N + bn + wn * 64 + nf * 16,
                acc[mf][nf], N, wmma::mem_row_major);
}

// ---------------------------------------------------------------------------
// Epilogue 1: g_x1[perm(row)] = x[perm(row)] + gm * g_tmp[row]   (window->x order)
// ---------------------------------------------------------------------------
__global__ void ep_proj_kernel(const float* __restrict__ x) {
    size_t i4 = (size_t)blockIdx.x * blockDim.x + threadIdx.x;  // float4 index
    int row = (int)(i4 >> 6);
    int c4  = ((int)i4 & 63) * 4;
    int b = row >> 12, t = row & 63, widx = (row >> 6) & 63;
    int wh = (widx >> 3) & 7, ww = widx & 7;
    int pr = (wh * 8 + (t >> 3) + 4) & 63;
    int pc = (ww * 8 + (t & 7) + 4) & 63;
    size_t prow = (size_t)(b * 4096 + pr * 64 + pc);

    float4 v  = *(const float4*)(g_tmp + (size_t)row * 256 + c4);
    float4 xr = __ldg((const float4*)(x + prow * 256 + c4));
    const float* gm = g_ada + b * 1536 + 512 + c4;
    float4 o = make_float4(xr.x + gm[0] * v.x, xr.y + gm[1] * v.y,
                           xr.z + gm[2] * v.z, xr.w + gm[3] * v.w);
    *(float4*)(g_x1 + prow * 256 + c4) = o;
}

// ---------------------------------------------------------------------------
// Epilogue 2: out = g_x1 + gp * g_tmp   (plain layout)
// ---------------------------------------------------------------------------
__global__ void ep_fc2_kernel(float* __restrict__ out) {
    size_t i4 = (size_t)blockIdx.x * blockDim.x + threadIdx.x;
    int row = (int)(i4 >> 6);
    int c4  = ((int)i4 & 63) * 4;
    int b = row >> 12;

    float4 v  = *(const float4*)(g_tmp + (size_t)row * 256 + c4);
    float4 xr = *(const float4*)(g_x1 + (size_t)row * 256 + c4);
    const float* gp = g_ada + b * 1536 + 1280 + c4;
    float4 o = make_float4(xr.x + gp[0] * v.x, xr.y + gp[1] * v.y,
                           xr.z + gp[2] * v.z, xr.w + gp[3] * v.w);
    *(float4*)(out + (size_t)row * 256 + c4) = o;
}

// ---------------------------------------------------------------------------
extern "C" void kernel_launch(void* const* d_in, const int* in_sizes, int n_in,
                              void* d_out, int out_size) {
    const float* x       = (const float*)d_in[0];
    const float* cond    = (const float*)d_in[1];
    const float* norm1_g = (const float*)d_in[2];
    const float* norm1_b = (const float*)d_in[3];
    const float* w_qkv   = (const float*)d_in[4];
    const float* b_qkv   = (const float*)d_in[5];
    const float* rel_b   = (const float*)d_in[6];
    const float* w_proj  = (const float*)d_in[7];
    const float* b_proj  = (const float*)d_in[8];
    const float* norm2_g = (const float*)d_in[9];
    const float* norm2_b = (const float*)d_in[10];
    const float* w_fc1   = (const float*)d_in[11];
    const float* b_fc1   = (const float*)d_in[12];
    const float* w_fc2   = (const float*)d_in[13];
    const float* b_fc2   = (const float*)d_in[14];
    const float* w_ada   = (const float*)d_in[15];
    const float* b_ada   = (const float*)d_in[16];
    float* out = (float*)d_out;

    float* d_qkv; cudaGetSymbolAddress((void**)&d_qkv, g_qkv);
    float* d_tmp; cudaGetSymbolAddress((void**)&d_tmp, g_tmp);
    float* d_mlp; cudaGetSymbolAddress((void**)&d_mlp, g_mlp);

    ada_kernel<<<16, 256>>>(cond, w_ada, b_ada);
    ln_mod_kernel<0><<<8192, 256>>>(x, norm1_g, norm1_b);
    gemm16_kernel<0><<<dim3(6, 512), 256>>>(w_qkv, b_qkv, d_qkv);
    attn_kernel<<<dim3(1024, 8), 64>>>(rel_b);
    gemm16_kernel<1><<<dim3(2, 512), 256>>>(w_proj, b_proj, d_tmp);
    ep_proj_kernel<<<16384, 256>>>(x);
    ln_mod_kernel<1><<<8192, 256>>>(x, norm2_g, norm2_b);
    gemm16_kernel<2><<<dim3(8, 512), 256>>>(w_fc1, b_fc1, d_mlp);
    gemm16_kernel<3><<<dim3(2, 512), 256>>>(w_fc2, b_fc2, d_tmp);
    ep_fc2_kernel<<<16384, 256>>>(out);
}

// round 4
// speedup vs baseline: 2.5924x; 1.7657x over previous
#include <cuda_runtime.h>
#include <cuda_bf16.h>
#include <cuda_pipeline_primitives.h>
#include <mma.h>
#include <math.h>

using namespace nvcuda;

// ---------------------------------------------------------------------------
// WITT AdaLN Swin block. bf16 tensor-core pipeline.
// B=16, H=W=64, C=256, NH=8, HD=32, WS=8, SS=4, N=64, NWIN=64, MLP_H=1024.
// TOK = 65536.
// ---------------------------------------------------------------------------

#define TOK 65536
typedef __nv_bfloat16 bf16;

__device__ __align__(16) float g_ada  [16 * 1536];
__device__ __align__(16) bf16  g_wb   [786432];             // qkv|proj|fc1|fc2 bf16
__device__ __align__(16) bf16  g_hwinh[(size_t)TOK * 256];  // LN1+mod, window order
__device__ __align__(16) bf16  g_qkvh [(size_t)TOK * 768];  // qkv+bias, window order
__device__ __align__(16) bf16  g_attnh[(size_t)TOK * 256];  // attn out, window order
__device__ __align__(16) float g_x1   [(size_t)TOK * 256];  // x after 1st residual (fp32!)
__device__ __align__(16) bf16  g_h2h  [(size_t)TOK * 256];  // LN2+mod
__device__ __align__(16) bf16  g_mlph [(size_t)TOK * 1024]; // GELU(fc1)

#define WOFF_QKV  0
#define WOFF_PROJ 196608
#define WOFF_FC1  262144
#define WOFF_FC2  524288

__device__ __forceinline__ uint32_t packbf(float a, float b) {
    __nv_bfloat162 t = __floats2bfloat162_rn(a, b);
    return *reinterpret_cast<uint32_t*>(&t);
}

// ---------------------------------------------------------------------------
// fp32 -> bf16 converter (weights)
// ---------------------------------------------------------------------------
__global__ void cvt_kernel(const float* __restrict__ src, bf16* __restrict__ dst, int n4) {
    int i = blockIdx.x * blockDim.x + threadIdx.x;
    if (i >= n4) return;
    float4 v = __ldg((const float4*)(src) + i);
    uint2 u;
    u.x = packbf(v.x, v.y);
    u.y = packbf(v.z, v.w);
    *((uint2*)dst + i) = u;
}

// ---------------------------------------------------------------------------
// ada = silu(cond) @ w_ada + b_ada   [16,1536]
// ---------------------------------------------------------------------------
__global__ void ada_kernel(const float* __restrict__ cond,
                           const float* __restrict__ w_ada,
                           const float* __restrict__ b_ada) {
    __shared__ float sc[256];
    int b = blockIdx.x, t = threadIdx.x;
    float v = cond[b * 256 + t];
    sc[t] = v / (1.0f + expf(-v));
    __syncthreads();
    for (int j = t; j < 1536; j += 256) {
        float acc = b_ada[j];
        #pragma unroll 4
        for (int i = 0; i < 256; i++) acc = fmaf(sc[i], __ldg(&w_ada[i * 1536 + j]), acc);
        g_ada[b * 1536 + j] = acc;
    }
}

// ---------------------------------------------------------------------------
// LN + AdaLN modulation -> bf16. PASS 0: roll(-4,-4)+window partition from x.
// PASS 1: plain (g_x1 fp32 -> g_h2h). One warp per token.
// ---------------------------------------------------------------------------
template <int PASS>
__global__ void ln_mod_kernel(const float* __restrict__ xin,
                              const float* __restrict__ gamma,
                              const float* __restrict__ beta) {
    int gw   = (blockIdx.x * blockDim.x + threadIdx.x) >> 5;
    int lane = threadIdx.x & 31;
    int b = gw >> 12;

    const float* src;
    bf16* dst;
    if (PASS == 0) {
        int t = gw & 63, widx = (gw >> 6) & 63;
        int wh = (widx >> 3) & 7, ww = widx & 7;
        int sr  = (wh * 8 + (t >> 3) + 4) & 63;
        int sc2 = (ww * 8 + (t & 7) + 4) & 63;
        src = xin + ((size_t)(b * 4096 + sr * 64 + sc2)) * 256;
        dst = g_hwinh + (size_t)gw * 256;
    } else {
        src = g_x1 + (size_t)gw * 256;
        dst = g_h2h + (size_t)gw * 256;
    }

    float4 v0 = *(const float4*)(src + lane * 8);
    float4 v1 = *(const float4*)(src + lane * 8 + 4);
    float e[8] = {v0.x, v0.y, v0.z, v0.w, v1.x, v1.y, v1.z, v1.w};

    float s = 0.f, q = 0.f;
    #pragma unroll
    for (int j = 0; j < 8; j++) { s += e[j]; q += e[j] * e[j]; }
    #pragma unroll
    for (int off = 16; off > 0; off >>= 1) {
        s += __shfl_xor_sync(0xffffffffu, s, off);
        q += __shfl_xor_sync(0xffffffffu, q, off);
    }
    float mean = s * (1.0f / 256.0f);
    float var  = q * (1.0f / 256.0f) - mean * mean;
    float rstd = rsqrtf(var + 1e-5f);

    const float* scl = g_ada + b * 1536 + (PASS == 0 ? 256 : 1024);
    const float* sft = g_ada + b * 1536 + (PASS == 0 ? 0   : 768);

    int ch = lane * 8;
    float o[8];
    #pragma unroll
    for (int j = 0; j < 8; j++) {
        float y = (e[j] - mean) * rstd * __ldg(&gamma[ch + j]) + __ldg(&beta[ch + j]);
        o[j] = y * (1.0f + scl[ch + j]) + sft[ch + j];
    }
    uint4 u;
    u.x = packbf(o[0], o[1]); u.y = packbf(o[2], o[3]);
    u.z = packbf(o[4], o[5]); u.w = packbf(o[6], o[7]);
    *(uint4*)(dst + ch) = u;
}

// ---------------------------------------------------------------------------
// Attention per (window, head). 64 threads = one query row each.
// float4-vectorized smem K/V; rel_bias staged in smem; unnormalized softmax.
// ---------------------------------------------------------------------------
__global__ void attn_kernel(const float* __restrict__ rel_bias) {
    __shared__ float4 ks4[64][9];
    __shared__ float4 vs4[64][9];
    __shared__ float  sb[225];
    int widx = blockIdx.x;
    int h    = blockIdx.y;
    int n    = threadIdx.x;

    for (int i = n; i < 225; i += 64) sb[i] = __ldg(&rel_bias[i * 8 + h]);

    const bf16* rowp = g_qkvh + (size_t)widx * 64 * 768 + (size_t)n * 768 + h * 32;
    const float scale = 0.17677669529663687f;
    float q[32];
    #pragma unroll
    for (int j = 0; j < 4; j++) {      // 8 bf16 per uint4
        uint4 uq = *(const uint4*)(rowp + j * 8);
        uint4 uk = *(const uint4*)(rowp + 256 + j * 8);
        uint4 uv = *(const uint4*)(rowp + 512 + j * 8);
        const uint32_t* pq = &uq.x;
        const uint32_t* pk = &uk.x;
        const uint32_t* pv = &uv.x;
        float kf[8], vf[8];
        #pragma unroll
        for (int p = 0; p < 4; p++) {
            float2 fq = __bfloat1622float2(*(const __nv_bfloat162*)&pq[p]);
            q[j * 8 + p * 2]     = fq.x * scale;
            q[j * 8 + p * 2 + 1] = fq.y * scale;
            float2 fk = __bfloat1622float2(*(const __nv_bfloat162*)&pk[p]);
            kf[p * 2] = fk.x; kf[p * 2 + 1] = fk.y;
            float2 fv = __bfloat1622float2(*(const __nv_bfloat162*)&pv[p]);
            vf[p * 2] = fv.x; vf[p * 2 + 1] = fv.y;
        }
        ks4[n][j * 2]     = make_float4(kf[0], kf[1], kf[2], kf[3]);
        ks4[n][j * 2 + 1] = make_float4(kf[4], kf[5], kf[6], kf[7]);
        vs4[n][j * 2]     = make_float4(vf[0], vf[1], vf[2], vf[3]);
        vs4[n][j * 2 + 1] = make_float4(vf[4], vf[5], vf[6], vf[7]);
    }
    __syncthreads();

    int wh = (widx >> 3) & 7, ww = widx & 7;
    int i1 = n >> 3, j1 = n & 7;
    int rv = wh * 8 + i1, cv = ww * 8 + j1;
    int idn = (rv < 56 ? 0 : (rv < 60 ? 1 : 2)) * 3 + (cv < 56 ? 0 : (cv < 60 ? 1 : 2));

    float o[32];
    #pragma unroll
    for (int d = 0; d < 32; d++) o[d] = 0.f;
    float sum = 0.f;

    for (int m = 0; m < 64; m++) {
        float s = 0.f;
        #pragma unroll
        for (int j = 0; j < 8; j++) {
            float4 kv = ks4[m][j];
            s = fmaf(q[j * 4 + 0], kv.x, s);
            s = fmaf(q[j * 4 + 1], kv.y, s);
            s = fmaf(q[j * 4 + 2], kv.z, s);
            s = fmaf(q[j * 4 + 3], kv.w, s);
        }
        int i2 = m >> 3, j2 = m & 7;
        s += sb[(i1 - i2 + 7) * 15 + (j1 - j2 + 7)];
        int rv2 = wh * 8 + i2, cv2 = ww * 8 + j2;
        int idm = (rv2 < 56 ? 0 : (rv2 < 60 ? 1 : 2)) * 3 +
                  (cv2 < 56 ? 0 : (cv2 < 60 ? 1 : 2));
        if (idm != idn) s -= 100.0f;
        float p = __expf(s);
        sum += p;
        #pragma unroll
        for (int j = 0; j < 8; j++) {
            float4 vv = vs4[m][j];
            o[j * 4 + 0] = fmaf(p, vv.x, o[j * 4 + 0]);
            o[j * 4 + 1] = fmaf(p, vv.y, o[j * 4 + 1]);
            o[j * 4 + 2] = fmaf(p, vv.z, o[j * 4 + 2]);
            o[j * 4 + 3] = fmaf(p, vv.w, o[j * 4 + 3]);
        }
    }
    float inv = 1.0f / sum;

    bf16* outp = g_attnh + (size_t)(widx * 64 + n) * 256 + h * 32;
    #pragma unroll
    for (int j = 0; j < 4; j++) {
        uint4 u;
        u.x = packbf(o[j*8+0]*inv, o[j*8+1]*inv);
        u.y = packbf(o[j*8+2]*inv, o[j*8+3]*inv);
        u.z = packbf(o[j*8+4]*inv, o[j*8+5]*inv);
        u.w = packbf(o[j*8+6]*inv, o[j*8+7]*inv);
        *(uint4*)(outp + j * 8) = u;
    }
}

// ---------------------------------------------------------------------------
// bf16 wmma GEMM, 128x128 tile, BK=64, cp.async 2-stage pipeline, fused epilogue.
// MODE 0: g_qkvh  = bf16(g_hwinh @ Wqkv + b)                       N=768 K=256
// MODE 1: g_x1[perm] = x[perm] + gm * (g_attnh @ Wproj + b)        N=256 K=256
// MODE 2: g_mlph  = bf16(gelu(g_h2h @ Wfc1 + b))                   N=1024 K=256
// MODE 3: out     = g_x1 + gp * (g_mlph @ Wfc2 + b)                N=256 K=1024
// ---------------------------------------------------------------------------
#define AS_STRIDE 72
#define BS_STRIDE 136
#define STAGE_BYTES (128 * AS_STRIDE * 2 + 64 * BS_STRIDE * 2)   // 18432+17408=35840
#define GEMM_SMEM   (2 * STAGE_BYTES)                             // 71680

template <int MODE>
__global__ void gemm_bf16(const float* __restrict__ bias,
                          const float* __restrict__ xres,
                          float* __restrict__ outp) {
    constexpr int K = (MODE == 3) ? 1024 : 256;
    constexpr int N = (MODE == 0) ? 768 : (MODE == 2) ? 1024 : 256;
    constexpr int NIT = K / 64;
    const bf16* A = (MODE == 0) ? g_hwinh : (MODE == 1) ? g_attnh
                  : (MODE == 2) ? g_h2h   : g_mlph;
    const bf16* W = g_wb + ((MODE == 0) ? WOFF_QKV : (MODE == 1) ? WOFF_PROJ
                         : (MODE == 2) ? WOFF_FC1 : WOFF_FC2);

    extern __shared__ char dsm[];
    int tid = threadIdx.x;
    int warp = tid >> 5;
    int wm = warp & 3, wn = warp >> 2;
    int bm = blockIdx.y * 128, bn = blockIdx.x * 128;

    wmma::fragment<wmma::accumulator, 16, 16, 16, float> acc[2][4];
    #pragma unroll
    for (int mf = 0; mf < 2; mf++)
        #pragma unroll
        for (int nf = 0; nf < 4; nf++)
            wmma::fill_fragment(acc[mf][nf], 0.0f);

    const bf16* Abase = A + (size_t)bm * K;

    auto issue_stage = [&](int it, int buf) {
        bf16* As = (bf16*)(dsm + buf * STAGE_BYTES);
        bf16* Bs = (bf16*)(dsm + buf * STAGE_BYTES + 128 * AS_STRIDE * 2);
        int k0 = it * 64;
        #pragma unroll
        for (int t = 0; t < 4; t++) {                 // A: 128 rows x 8 chunks
            int idx = tid + t * 256;
            int r = idx >> 3, c = (idx & 7) * 8;
            __pipeline_memcpy_async(As + r * AS_STRIDE + c,
                                    Abase + (size_t)r * K + k0 + c, 16);
        }
        #pragma unroll
        for (int t = 0; t < 4; t++) {                 // B: 64 rows x 16 chunks
            int idx = tid + t * 256;
            int r = idx >> 4, c = (idx & 15) * 8;
            __pipeline_memcpy_async(Bs + r * BS_STRIDE + c,
                                    W + (size_t)(k0 + r) * N + bn + c, 16);
        }
        __pipeline_commit();
    };

    issue_stage(0, 0);
    for (int it = 0; it < NIT; it++) {
        if (it + 1 < NIT) issue_stage(it + 1, (it + 1) & 1);
        __pipeline_wait_prior((it + 1 < NIT) ? 1 : 0);
        __syncthreads();
        const bf16* As = (const bf16*)(dsm + (it & 1) * STAGE_BYTES);
        const bf16* Bs = (const bf16*)(dsm + (it & 1) * STAGE_BYTES + 128 * AS_STRIDE * 2);
        #pragma unroll
        for (int kk = 0; kk < 64; kk += 16) {
            wmma::fragment<wmma::matrix_a, 16, 16, 16, bf16, wmma::row_major> af[2];
            wmma::fragment<wmma::matrix_b, 16, 16, 16, bf16, wmma::row_major> bf[4];
            #pragma unroll
            for (int mf = 0; mf < 2; mf++)
                wmma::load_matrix_sync(af[mf], As + (wm * 32 + mf * 16) * AS_STRIDE + kk, AS_STRIDE);
            #pragma unroll
            for (int nf = 0; nf < 4; nf++)
                wmma::load_matrix_sync(bf[nf], Bs + kk * BS_STRIDE + wn * 64 + nf * 16, BS_STRIDE);
            #pragma unroll
            for (int mf = 0; mf < 2; mf++)
                #pragma unroll
                for (int nf = 0; nf < 4; nf++)
                    wmma::mma_sync(acc[mf][nf], af[mf], bf[nf], acc[mf][nf]);
        }
        __syncthreads();
    }

    // --- epilogue via smem roundtrip (alias stage buffers) ---
    float* epi = (float*)dsm;   // 128x128 fp32 = 64KB
    #pragma unroll
    for (int mf = 0; mf < 2; mf++)
        #pragma unroll
        for (int nf = 0; nf < 4; nf++)
            wmma::store_matrix_sync(epi + (wm * 32 + mf * 16) * 128 + wn * 64 + nf * 16,
                                    acc[mf][nf], 128, wmma::mem_row_major);
    __syncthreads();

    #pragma unroll
    for (int t = 0; t < 8; t++) {
        int ch = tid + t * 256;           // 2048 chunks of 8 cols
        int r = ch >> 4;
        int c8 = (ch & 15) * 8;
        int col = bn + c8;
        int row = bm + r;
        float v[8];
        *(float4*)(v)     = *(const float4*)(epi + r * 128 + c8);
        *(float4*)(v + 4) = *(const float4*)(epi + r * 128 + c8 + 4);
        #pragma unroll
        for (int j = 0; j < 8; j++) v[j] += __ldg(&bias[col + j]);

        if (MODE == 0) {
            uint4 u;
            u.x = packbf(v[0], v[1]); u.y = packbf(v[2], v[3]);
            u.z = packbf(v[4], v[5]); u.w = packbf(v[6], v[7]);
            *(uint4*)(g_qkvh + (size_t)row * 768 + col) = u;
        } else if (MODE == 1) {
            int b = row >> 12, tt = row & 63, widx = (row >> 6) & 63;
            int wh = (widx >> 3) & 7, ww = widx & 7;
            int pr = (wh * 8 + (tt >> 3) + 4) & 63;
            int pc = (ww * 8 + (tt & 7) + 4) & 63;
            size_t prow = (size_t)(b * 4096 + pr * 64 + pc);
            const float* gm = g_ada + b * 1536 + 512;
            float o[8];
            #pragma unroll
            for (int j = 0; j < 8; j++)
                o[j] = __ldg(&xres[prow * 256 + col + j]) + gm[col + j] * v[j];
            *(float4*)(g_x1 + prow * 256 + col)     = *(float4*)(o);
            *(float4*)(g_x1 + prow * 256 + col + 4) = *(float4*)(o + 4);
        } else if (MODE == 2) {
            uint4 u;
            float o[8];
            #pragma unroll
            for (int j = 0; j < 8; j++)
                o[j] = 0.5f * v[j] * (1.0f + erff(v[j] * 0.70710678118654752f));
            u.x = packbf(o[0], o[1]); u.y = packbf(o[2], o[3]);
            u.z = packbf(o[4], o[5]); u.w = packbf(o[6], o[7]);
            *(uint4*)(g_mlph + (size_t)row * 1024 + col) = u;
        } else {
            int b = row >> 12;
            const float* gp = g_ada + b * 1536 + 1280;
            const float* x1 = g_x1 + (size_t)row * 256 + col;
            float o[8];
            #pragma unroll
            for (int j = 0; j < 8; j++)
                o[j] = x1[j] + gp[col + j] * v[j];
            *(float4*)(outp + (size_t)row * 256 + col)     = *(float4*)(o);
            *(float4*)(outp + (size_t)row * 256 + col + 4) = *(float4*)(o + 4);
        }
    }
}

// ---------------------------------------------------------------------------
extern "C" void kernel_launch(void* const* d_in, const int* in_sizes, int n_in,
                              void* d_out, int out_size) {
    const float* x       = (const float*)d_in[0];
    const float* cond    = (const float*)d_in[1];
    const float* norm1_g = (const float*)d_in[2];
    const float* norm1_b = (const float*)d_in[3];
    const float* w_qkv   = (const float*)d_in[4];
    const float* b_qkv   = (const float*)d_in[5];
    const float* rel_b   = (const float*)d_in[6];
    const float* w_proj  = (const float*)d_in[7];
    const float* b_proj  = (const float*)d_in[8];
    const float* norm2_g = (const float*)d_in[9];
    const float* norm2_b = (const float*)d_in[10];
    const float* w_fc1   = (const float*)d_in[11];
    const float* b_fc1   = (const float*)d_in[12];
    const float* w_fc2   = (const float*)d_in[13];
    const float* b_fc2   = (const float*)d_in[14];
    const float* w_ada   = (const float*)d_in[15];
    const float* b_ada   = (const float*)d_in[16];
    float* out = (float*)d_out;

    bf16* d_wb; cudaGetSymbolAddress((void**)&d_wb, g_wb);

    cudaFuncSetAttribute(gemm_bf16<0>, cudaFuncAttributeMaxDynamicSharedMemorySize, GEMM_SMEM);
    cudaFuncSetAttribute(gemm_bf16<1>, cudaFuncAttributeMaxDynamicSharedMemorySize, GEMM_SMEM);
    cudaFuncSetAttribute(gemm_bf16<2>, cudaFuncAttributeMaxDynamicSharedMemorySize, GEMM_SMEM);
    cudaFuncSetAttribute(gemm_bf16<3>, cudaFuncAttributeMaxDynamicSharedMemorySize, GEMM_SMEM);

    cvt_kernel<<<192, 256>>>(w_qkv,  d_wb + WOFF_QKV,  196608 / 4);
    cvt_kernel<<<64,  256>>>(w_proj, d_wb + WOFF_PROJ, 65536 / 4);
    cvt_kernel<<<256, 256>>>(w_fc1,  d_wb + WOFF_FC1,  262144 / 4);
    cvt_kernel<<<256, 256>>>(w_fc2,  d_wb + WOFF_FC2,  262144 / 4);
    ada_kernel<<<16, 256>>>(cond, w_ada, b_ada);
    ln_mod_kernel<0><<<8192, 256>>>(x, norm1_g, norm1_b);
    gemm_bf16<0><<<dim3(6, 512), 256, GEMM_SMEM>>>(b_qkv, nullptr, nullptr);
    attn_kernel<<<dim3(1024, 8), 64>>>(rel_b);
    gemm_bf16<1><<<dim3(2, 512), 256, GEMM_SMEM>>>(b_proj, x, nullptr);
    ln_mod_kernel<1><<<8192, 256>>>(nullptr, norm2_g, norm2_b);
    gemm_bf16<2><<<dim3(8, 512), 256, GEMM_SMEM>>>(b_fc1, nullptr, nullptr);
    gemm_bf16<3><<<dim3(2, 512), 256, GEMM_SMEM>>>(b_fc2, nullptr, out);
}

// round 5
// speedup vs baseline: 2.5948x; 1.0009x over previous
#include <cuda_runtime.h>
#include <cuda_bf16.h>
#include <cuda_pipeline_primitives.h>
#include <mma.h>
#include <math.h>

using namespace nvcuda;

// ---------------------------------------------------------------------------
// WITT AdaLN Swin block. bf16 tensor-core pipeline.
// B=16, H=W=64, C=256, NH=8, HD=32, WS=8, SS=4, N=64, NWIN=64, MLP_H=1024.
// TOK = 65536.
// ---------------------------------------------------------------------------

#define TOK 65536
typedef __nv_bfloat16 bf16;

__device__ __align__(16) float g_ada  [16 * 1536];
__device__ __align__(16) bf16  g_wb   [786432];             // qkv|proj|fc1|fc2 bf16
__device__ __align__(16) bf16  g_hwinh[(size_t)TOK * 256];  // LN1+mod, window order
__device__ __align__(16) bf16  g_qkvh [(size_t)TOK * 768];  // qkv+bias, window order
__device__ __align__(16) bf16  g_attnh[(size_t)TOK * 256];  // attn out, window order
__device__ __align__(16) float g_x1   [(size_t)TOK * 256];  // x after 1st residual (fp32!)
__device__ __align__(16) bf16  g_h2h  [(size_t)TOK * 256];  // LN2+mod
__device__ __align__(16) bf16  g_mlph [(size_t)TOK * 1024]; // GELU(fc1)

#define WOFF_QKV  0
#define WOFF_PROJ 196608
#define WOFF_FC1  262144
#define WOFF_FC2  524288

__device__ __forceinline__ uint32_t packbf(float a, float b) {
    __nv_bfloat162 t = __floats2bfloat162_rn(a, b);
    return *reinterpret_cast<uint32_t*>(&t);
}

// ---------------------------------------------------------------------------
// fp32 -> bf16 converter (weights)
// ---------------------------------------------------------------------------
__global__ void cvt_kernel(const float* __restrict__ src, bf16* __restrict__ dst, int n4) {
    int i = blockIdx.x * blockDim.x + threadIdx.x;
    if (i >= n4) return;
    float4 v = __ldg((const float4*)(src) + i);
    uint2 u;
    u.x = packbf(v.x, v.y);
    u.y = packbf(v.z, v.w);
    *((uint2*)dst + i) = u;
}

// ---------------------------------------------------------------------------
// ada = silu(cond) @ w_ada + b_ada   [16,1536]
// ---------------------------------------------------------------------------
__global__ void ada_kernel(const float* __restrict__ cond,
                           const float* __restrict__ w_ada,
                           const float* __restrict__ b_ada) {
    __shared__ float sc[256];
    int b = blockIdx.x, t = threadIdx.x;
    float v = cond[b * 256 + t];
    sc[t] = v / (1.0f + expf(-v));
    __syncthreads();
    for (int j = t; j < 1536; j += 256) {
        float acc = b_ada[j];
        #pragma unroll 4
        for (int i = 0; i < 256; i++) acc = fmaf(sc[i], __ldg(&w_ada[i * 1536 + j]), acc);
        g_ada[b * 1536 + j] = acc;
    }
}

// ---------------------------------------------------------------------------
// LN + AdaLN modulation -> bf16. PASS 0: roll(-4,-4)+window partition from x.
// PASS 1: plain (g_x1 fp32 -> g_h2h). One warp per token.
// ---------------------------------------------------------------------------
template <int PASS>
__global__ void ln_mod_kernel(const float* __restrict__ xin,
                              const float* __restrict__ gamma,
                              const float* __restrict__ beta) {
    int gw   = (blockIdx.x * blockDim.x + threadIdx.x) >> 5;
    int lane = threadIdx.x & 31;
    int b = gw >> 12;

    const float* src;
    bf16* dst;
    if (PASS == 0) {
        int t = gw & 63, widx = (gw >> 6) & 63;
        int wh = (widx >> 3) & 7, ww = widx & 7;
        int sr  = (wh * 8 + (t >> 3) + 4) & 63;
        int sc2 = (ww * 8 + (t & 7) + 4) & 63;
        src = xin + ((size_t)(b * 4096 + sr * 64 + sc2)) * 256;
        dst = g_hwinh + (size_t)gw * 256;
    } else {
        src = g_x1 + (size_t)gw * 256;
        dst = g_h2h + (size_t)gw * 256;
    }

    float4 v0 = *(const float4*)(src + lane * 8);
    float4 v1 = *(const float4*)(src + lane * 8 + 4);
    float e[8] = {v0.x, v0.y, v0.z, v0.w, v1.x, v1.y, v1.z, v1.w};

    float s = 0.f, q = 0.f;
    #pragma unroll
    for (int j = 0; j < 8; j++) { s += e[j]; q += e[j] * e[j]; }
    #pragma unroll
    for (int off = 16; off > 0; off >>= 1) {
        s += __shfl_xor_sync(0xffffffffu, s, off);
        q += __shfl_xor_sync(0xffffffffu, q, off);
    }
    float mean = s * (1.0f / 256.0f);
    float var  = q * (1.0f / 256.0f) - mean * mean;
    float rstd = rsqrtf(var + 1e-5f);

    const float* scl = g_ada + b * 1536 + (PASS == 0 ? 256 : 1024);
    const float* sft = g_ada + b * 1536 + (PASS == 0 ? 0   : 768);

    int ch = lane * 8;
    float o[8];
    #pragma unroll
    for (int j = 0; j < 8; j++) {
        float y = (e[j] - mean) * rstd * __ldg(&gamma[ch + j]) + __ldg(&beta[ch + j]);
        o[j] = y * (1.0f + scl[ch + j]) + sft[ch + j];
    }
    uint4 u;
    u.x = packbf(o[0], o[1]); u.y = packbf(o[2], o[3]);
    u.z = packbf(o[4], o[5]); u.w = packbf(o[6], o[7]);
    *(uint4*)(dst + ch) = u;
}

// ---------------------------------------------------------------------------
// Attention per (window, head). 64 threads = one query row each.
// float4-vectorized smem K/V; rel_bias staged in smem; unnormalized softmax.
// ---------------------------------------------------------------------------
__global__ void attn_kernel(const float* __restrict__ rel_bias) {
    __shared__ float4 ks4[64][9];
    __shared__ float4 vs4[64][9];
    __shared__ float  sb[225];
    int widx = blockIdx.x;
    int h    = blockIdx.y;
    int n    = threadIdx.x;

    for (int i = n; i < 225; i += 64) sb[i] = __ldg(&rel_bias[i * 8 + h]);

    const bf16* rowp = g_qkvh + (size_t)widx * 64 * 768 + (size_t)n * 768 + h * 32;
    const float scale = 0.17677669529663687f;
    float q[32];
    #pragma unroll
    for (int j = 0; j < 4; j++) {      // 8 bf16 per uint4
        uint4 uq = *(const uint4*)(rowp + j * 8);
        uint4 uk = *(const uint4*)(rowp + 256 + j * 8);
        uint4 uv = *(const uint4*)(rowp + 512 + j * 8);
        const uint32_t* pq = &uq.x;
        const uint32_t* pk = &uk.x;
        const uint32_t* pv = &uv.x;
        float kf[8], vf[8];
        #pragma unroll
        for (int p = 0; p < 4; p++) {
            float2 fq = __bfloat1622float2(*(const __nv_bfloat162*)&pq[p]);
            q[j * 8 + p * 2]     = fq.x * scale;
            q[j * 8 + p * 2 + 1] = fq.y * scale;
            float2 fk = __bfloat1622float2(*(const __nv_bfloat162*)&pk[p]);
            kf[p * 2] = fk.x; kf[p * 2 + 1] = fk.y;
            float2 fv = __bfloat1622float2(*(const __nv_bfloat162*)&pv[p]);
            vf[p * 2] = fv.x; vf[p * 2 + 1] = fv.y;
        }
        ks4[n][j * 2]     = make_float4(kf[0], kf[1], kf[2], kf[3]);
        ks4[n][j * 2 + 1] = make_float4(kf[4], kf[5], kf[6], kf[7]);
        vs4[n][j * 2]     = make_float4(vf[0], vf[1], vf[2], vf[3]);
        vs4[n][j * 2 + 1] = make_float4(vf[4], vf[5], vf[6], vf[7]);
    }
    __syncthreads();

    int wh = (widx >> 3) & 7, ww = widx & 7;
    int i1 = n >> 3, j1 = n & 7;
    int rv = wh * 8 + i1, cv = ww * 8 + j1;
    int idn = (rv < 56 ? 0 : (rv < 60 ? 1 : 2)) * 3 + (cv < 56 ? 0 : (cv < 60 ? 1 : 2));

    float o[32];
    #pragma unroll
    for (int d = 0; d < 32; d++) o[d] = 0.f;
    float sum = 0.f;

    for (int m = 0; m < 64; m++) {
        float s = 0.f;
        #pragma unroll
        for (int j = 0; j < 8; j++) {
            float4 kv = ks4[m][j];
            s = fmaf(q[j * 4 + 0], kv.x, s);
            s = fmaf(q[j * 4 + 1], kv.y, s);
            s = fmaf(q[j * 4 + 2], kv.z, s);
            s = fmaf(q[j * 4 + 3], kv.w, s);
        }
        int i2 = m >> 3, j2 = m & 7;
        s += sb[(i1 - i2 + 7) * 15 + (j1 - j2 + 7)];
        int rv2 = wh * 8 + i2, cv2 = ww * 8 + j2;
        int idm = (rv2 < 56 ? 0 : (rv2 < 60 ? 1 : 2)) * 3 +
                  (cv2 < 56 ? 0 : (cv2 < 60 ? 1 : 2));
        if (idm != idn) s -= 100.0f;
        float p = __expf(s);
        sum += p;
        #pragma unroll
        for (int j = 0; j < 8; j++) {
            float4 vv = vs4[m][j];
            o[j * 4 + 0] = fmaf(p, vv.x, o[j * 4 + 0]);
            o[j * 4 + 1] = fmaf(p, vv.y, o[j * 4 + 1]);
            o[j * 4 + 2] = fmaf(p, vv.z, o[j * 4 + 2]);
            o[j * 4 + 3] = fmaf(p, vv.w, o[j * 4 + 3]);
        }
    }
    float inv = 1.0f / sum;

    bf16* outp = g_attnh + (size_t)(widx * 64 + n) * 256 + h * 32;
    #pragma unroll
    for (int j = 0; j < 4; j++) {
        uint4 u;
        u.x = packbf(o[j*8+0]*inv, o[j*8+1]*inv);
        u.y = packbf(o[j*8+2]*inv, o[j*8+3]*inv);
        u.z = packbf(o[j*8+4]*inv, o[j*8+5]*inv);
        u.w = packbf(o[j*8+6]*inv, o[j*8+7]*inv);
        *(uint4*)(outp + j * 8) = u;
    }
}

// ---------------------------------------------------------------------------
// bf16 wmma GEMM, 128x128 tile, BK=64, cp.async 2-stage pipeline, fused epilogue.
// MODE 0: g_qkvh  = bf16(g_hwinh @ Wqkv + b)                       N=768 K=256
// MODE 1: g_x1[perm] = x[perm] + gm * (g_attnh @ Wproj + b)        N=256 K=256
// MODE 2: g_mlph  = bf16(gelu(g_h2h @ Wfc1 + b))                   N=1024 K=256
// MODE 3: out     = g_x1 + gp * (g_mlph @ Wfc2 + b)                N=256 K=1024
// ---------------------------------------------------------------------------
#define AS_STRIDE 72
#define BS_STRIDE 136
#define STAGE_BYTES (128 * AS_STRIDE * 2 + 64 * BS_STRIDE * 2)   // 18432+17408=35840
#define GEMM_SMEM   (2 * STAGE_BYTES)                             // 71680

template <int MODE>
__global__ void gemm_bf16(const float* __restrict__ bias,
                          const float* __restrict__ xres,
                          float* __restrict__ outp) {
    constexpr int K = (MODE == 3) ? 1024 : 256;
    constexpr int N = (MODE == 0) ? 768 : (MODE == 2) ? 1024 : 256;
    constexpr int NIT = K / 64;
    const bf16* A = (MODE == 0) ? g_hwinh : (MODE == 1) ? g_attnh
                  : (MODE == 2) ? g_h2h   : g_mlph;
    const bf16* W = g_wb + ((MODE == 0) ? WOFF_QKV : (MODE == 1) ? WOFF_PROJ
                         : (MODE == 2) ? WOFF_FC1 : WOFF_FC2);

    extern __shared__ char dsm[];
    int tid = threadIdx.x;
    int warp = tid >> 5;
    int wm = warp & 3, wn = warp >> 2;
    int bm = blockIdx.y * 128, bn = blockIdx.x * 128;

    wmma::fragment<wmma::accumulator, 16, 16, 16, float> acc[2][4];
    #pragma unroll
    for (int mf = 0; mf < 2; mf++)
        #pragma unroll
        for (int nf = 0; nf < 4; nf++)
            wmma::fill_fragment(acc[mf][nf], 0.0f);

    const bf16* Abase = A + (size_t)bm * K;

    auto issue_stage = [&](int it, int buf) {
        bf16* As = (bf16*)(dsm + buf * STAGE_BYTES);
        bf16* Bs = (bf16*)(dsm + buf * STAGE_BYTES + 128 * AS_STRIDE * 2);
        int k0 = it * 64;
        #pragma unroll
        for (int t = 0; t < 4; t++) {                 // A: 128 rows x 8 chunks
            int idx = tid + t * 256;
            int r = idx >> 3, c = (idx & 7) * 8;
            __pipeline_memcpy_async(As + r * AS_STRIDE + c,
                                    Abase + (size_t)r * K + k0 + c, 16);
        }
        #pragma unroll
        for (int t = 0; t < 4; t++) {                 // B: 64 rows x 16 chunks
            int idx = tid + t * 256;
            int r = idx >> 4, c = (idx & 15) * 8;
            __pipeline_memcpy_async(Bs + r * BS_STRIDE + c,
                                    W + (size_t)(k0 + r) * N + bn + c, 16);
        }
        __pipeline_commit();
    };

    issue_stage(0, 0);
    for (int it = 0; it < NIT; it++) {
        if (it + 1 < NIT) issue_stage(it + 1, (it + 1) & 1);
        __pipeline_wait_prior((it + 1 < NIT) ? 1 : 0);
        __syncthreads();
        const bf16* As = (const bf16*)(dsm + (it & 1) * STAGE_BYTES);
        const bf16* Bs = (const bf16*)(dsm + (it & 1) * STAGE_BYTES + 128 * AS_STRIDE * 2);
        #pragma unroll
        for (int kk = 0; kk < 64; kk += 16) {
            wmma::fragment<wmma::matrix_a, 16, 16, 16, bf16, wmma::row_major> af[2];
            wmma::fragment<wmma::matrix_b, 16, 16, 16, bf16, wmma::row_major> bf[4];
            #pragma unroll
            for (int mf = 0; mf < 2; mf++)
                wmma::load_matrix_sync(af[mf], As + (wm * 32 + mf * 16) * AS_STRIDE + kk, AS_STRIDE);
            #pragma unroll
            for (int nf = 0; nf < 4; nf++)
                wmma::load_matrix_sync(bf[nf], Bs + kk * BS_STRIDE + wn * 64 + nf * 16, BS_STRIDE);
            #pragma unroll
            for (int mf = 0; mf < 2; mf++)
                #pragma unroll
                for (int nf = 0; nf < 4; nf++)
                    wmma::mma_sync(acc[mf][nf], af[mf], bf[nf], acc[mf][nf]);
        }
        __syncthreads();
    }

    // --- epilogue via smem roundtrip (alias stage buffers) ---
    float* epi = (float*)dsm;   // 128x128 fp32 = 64KB
    #pragma unroll
    for (int mf = 0; mf < 2; mf++)
        #pragma unroll
        for (int nf = 0; nf < 4; nf++)
            wmma::store_matrix_sync(epi + (wm * 32 + mf * 16) * 128 + wn * 64 + nf * 16,
                                    acc[mf][nf], 128, wmma::mem_row_major);
    __syncthreads();

    #pragma unroll
    for (int t = 0; t < 8; t++) {
        int ch = tid + t * 256;           // 2048 chunks of 8 cols
        int r = ch >> 4;
        int c8 = (ch & 15) * 8;
        int col = bn + c8;
        int row = bm + r;
        float v[8];
        *(float4*)(v)     = *(const float4*)(epi + r * 128 + c8);
        *(float4*)(v + 4) = *(const float4*)(epi + r * 128 + c8 + 4);
        #pragma unroll
        for (int j = 0; j < 8; j++) v[j] += __ldg(&bias[col + j]);

        if (MODE == 0) {
            uint4 u;
            u.x = packbf(v[0], v[1]); u.y = packbf(v[2], v[3]);
            u.z = packbf(v[4], v[5]); u.w = packbf(v[6], v[7]);
            *(uint4*)(g_qkvh + (size_t)row * 768 + col) = u;
        } else if (MODE == 1) {
            int b = row >> 12, tt = row & 63, widx = (row >> 6) & 63;
            int wh = (widx >> 3) & 7, ww = widx & 7;
            int pr = (wh * 8 + (tt >> 3) + 4) & 63;
            int pc = (ww * 8 + (tt & 7) + 4) & 63;
            size_t prow = (size_t)(b * 4096 + pr * 64 + pc);
            const float* gm = g_ada + b * 1536 + 512;
            float o[8];
            #pragma unroll
            for (int j = 0; j < 8; j++)
                o[j] = __ldg(&xres[prow * 256 + col + j]) + gm[col + j] * v[j];
            *(float4*)(g_x1 + prow * 256 + col)     = *(float4*)(o);
            *(float4*)(g_x1 + prow * 256 + col + 4) = *(float4*)(o + 4);
        } else if (MODE == 2) {
            uint4 u;
            float o[8];
            #pragma unroll
            for (int j = 0; j < 8; j++)
                o[j] = 0.5f * v[j] * (1.0f + erff(v[j] * 0.70710678118654752f));
            u.x = packbf(o[0], o[1]); u.y = packbf(o[2], o[3]);
            u.z = packbf(o[4], o[5]); u.w = packbf(o[6], o[7]);
            *(uint4*)(g_mlph + (size_t)row * 1024 + col) = u;
        } else {
            int b = row >> 12;
            const float* gp = g_ada + b * 1536 + 1280;
            const float* x1 = g_x1 + (size_t)row * 256 + col;
            float o[8];
            #pragma unroll
            for (int j = 0; j < 8; j++)
                o[j] = x1[j] + gp[col + j] * v[j];
            *(float4*)(outp + (size_t)row * 256 + col)     = *(float4*)(o);
            *(float4*)(outp + (size_t)row * 256 + col + 4) = *(float4*)(o + 4);
        }
    }
}

// ---------------------------------------------------------------------------
extern "C" void kernel_launch(void* const* d_in, const int* in_sizes, int n_in,
                              void* d_out, int out_size) {
    const float* x       = (const float*)d_in[0];
    const float* cond    = (const float*)d_in[1];
    const float* norm1_g = (const float*)d_in[2];
    const float* norm1_b = (const float*)d_in[3];
    const float* w_qkv   = (const float*)d_in[4];
    const float* b_qkv   = (const float*)d_in[5];
    const float* rel_b   = (const float*)d_in[6];
    const float* w_proj  = (const float*)d_in[7];
    const float* b_proj  = (const float*)d_in[8];
    const float* norm2_g = (const float*)d_in[9];
    const float* norm2_b = (const float*)d_in[10];
    const float* w_fc1   = (const float*)d_in[11];
    const float* b_fc1   = (const float*)d_in[12];
    const float* w_fc2   = (const float*)d_in[13];
    const float* b_fc2   = (const float*)d_in[14];
    const float* w_ada   = (const float*)d_in[15];
    const float* b_ada   = (const float*)d_in[16];
    float* out = (float*)d_out;

    bf16* d_wb; cudaGetSymbolAddress((void**)&d_wb, g_wb);

    cudaFuncSetAttribute(gemm_bf16<0>, cudaFuncAttributeMaxDynamicSharedMemorySize, GEMM_SMEM);
    cudaFuncSetAttribute(gemm_bf16<1>, cudaFuncAttributeMaxDynamicSharedMemorySize, GEMM_SMEM);
    cudaFuncSetAttribute(gemm_bf16<2>, cudaFuncAttributeMaxDynamicSharedMemorySize, GEMM_SMEM);
    cudaFuncSetAttribute(gemm_bf16<3>, cudaFuncAttributeMaxDynamicSharedMemorySize, GEMM_SMEM);

    cvt_kernel<<<192, 256>>>(w_qkv,  d_wb + WOFF_QKV,  196608 / 4);
    cvt_kernel<<<64,  256>>>(w_proj, d_wb + WOFF_PROJ, 65536 / 4);
    cvt_kernel<<<256, 256>>>(w_fc1,  d_wb + WOFF_FC1,  262144 / 4);
    cvt_kernel<<<256, 256>>>(w_fc2,  d_wb + WOFF_FC2,  262144 / 4);
    ada_kernel<<<16, 256>>>(cond, w_ada, b_ada);
    ln_mod_kernel<0><<<8192, 256>>>(x, norm1_g, norm1_b);
    gemm_bf16<0><<<dim3(6, 512), 256, GEMM_SMEM>>>(b_qkv, nullptr, nullptr);
    attn_kernel<<<dim3(1024, 8), 64>>>(rel_b);
    gemm_bf16<1><<<dim3(2, 512), 256, GEMM_SMEM>>>(b_proj, x, nullptr);
    ln_mod_kernel<1><<<8192, 256>>>(nullptr, norm2_g, norm2_b);
    gemm_bf16<2><<<dim3(8, 512), 256, GEMM_SMEM>>>(b_fc1, nullptr, nullptr);
    gemm_bf16<3><<<dim3(2, 512), 256, GEMM_SMEM>>>(b_fc2, nullptr, out);
}

// round 11
// speedup vs baseline: 2.7560x; 1.0621x over previous
#include <cuda_runtime.h>
#include <cuda_bf16.h>
#include <cuda_pipeline_primitives.h>
#include <mma.h>
#include <math.h>

using namespace nvcuda;

// ---------------------------------------------------------------------------
// WITT AdaLN Swin block. wmma bf16 GEMMs (HMMA; sm_100 target has no tcgen05)
// B=16, H=W=64, C=256, NH=8, HD=32, WS=8, SS=4, N=64, NWIN=64, MLP_H=1024.
// ---------------------------------------------------------------------------

#define TOK 65536
typedef __nv_bfloat16 bf16;

__device__ __align__(16) float g_ada  [16 * 1536];
__device__ __align__(16) bf16  g_wb   [786432];             // bf16 weights [K,N]
__device__ __align__(16) bf16  g_hwinh[(size_t)TOK * 256];
__device__ __align__(16) bf16  g_qkvh [(size_t)TOK * 768];
__device__ __align__(16) bf16  g_attnh[(size_t)TOK * 256];
__device__ __align__(16) float g_x1   [(size_t)TOK * 256];
__device__ __align__(16) bf16  g_h2h  [(size_t)TOK * 256];
__device__ __align__(16) bf16  g_mlph [(size_t)TOK * 1024];

#define WOFF_QKV  0
#define WOFF_PROJ 196608
#define WOFF_FC1  262144
#define WOFF_FC2  524288

__device__ __forceinline__ uint32_t packbf(float a, float b) {
    __nv_bfloat162 t = __floats2bfloat162_rn(a, b);
    return *reinterpret_cast<uint32_t*>(&t);
}

// ---------------------------------------------------------------------------
// fp32 -> bf16 converter (weights, [K,N] layout preserved)
// ---------------------------------------------------------------------------
__global__ void cvt_kernel(const float* __restrict__ src, bf16* __restrict__ dst, int n4) {
    int i = blockIdx.x * blockDim.x + threadIdx.x;
    if (i >= n4) return;
    float4 v = __ldg((const float4*)(src) + i);
    uint2 u;
    u.x = packbf(v.x, v.y);
    u.y = packbf(v.z, v.w);
    *((uint2*)dst + i) = u;
}

// ---------------------------------------------------------------------------
// ada = silu(cond) @ w_ada + b_ada   [16,1536]
// ---------------------------------------------------------------------------
__global__ void ada_kernel(const float* __restrict__ cond,
                           const float* __restrict__ w_ada,
                           const float* __restrict__ b_ada) {
    __shared__ float sc[256];
    int b = blockIdx.x, t = threadIdx.x;
    float v = cond[b * 256 + t];
    sc[t] = v / (1.0f + expf(-v));
    __syncthreads();
    for (int j = t; j < 1536; j += 256) {
        float acc = b_ada[j];
        #pragma unroll 4
        for (int i = 0; i < 256; i++) acc = fmaf(sc[i], __ldg(&w_ada[i * 1536 + j]), acc);
        g_ada[b * 1536 + j] = acc;
    }
}

// ---------------------------------------------------------------------------
// LN + AdaLN -> bf16. PASS 0: roll(-4,-4)+window partition; PASS 1: plain.
// ---------------------------------------------------------------------------
template <int PASS>
__global__ void ln_mod_kernel(const float* __restrict__ xin,
                              const float* __restrict__ gamma,
                              const float* __restrict__ beta) {
    int gw   = (blockIdx.x * blockDim.x + threadIdx.x) >> 5;
    int lane = threadIdx.x & 31;
    int b = gw >> 12;

    const float* src;
    bf16* dst;
    if (PASS == 0) {
        int t = gw & 63, widx = (gw >> 6) & 63;
        int wh = (widx >> 3) & 7, ww = widx & 7;
        int sr  = (wh * 8 + (t >> 3) + 4) & 63;
        int sc2 = (ww * 8 + (t & 7) + 4) & 63;
        src = xin + ((size_t)(b * 4096 + sr * 64 + sc2)) * 256;
        dst = g_hwinh + (size_t)gw * 256;
    } else {
        src = g_x1 + (size_t)gw * 256;
        dst = g_h2h + (size_t)gw * 256;
    }

    float4 v0 = *(const float4*)(src + lane * 8);
    float4 v1 = *(const float4*)(src + lane * 8 + 4);
    float e[8] = {v0.x, v0.y, v0.z, v0.w, v1.x, v1.y, v1.z, v1.w};

    float s = 0.f, q = 0.f;
    #pragma unroll
    for (int j = 0; j < 8; j++) { s += e[j]; q += e[j] * e[j]; }
    #pragma unroll
    for (int off = 16; off > 0; off >>= 1) {
        s += __shfl_xor_sync(0xffffffffu, s, off);
        q += __shfl_xor_sync(0xffffffffu, q, off);
    }
    float mean = s * (1.0f / 256.0f);
    float var  = q * (1.0f / 256.0f) - mean * mean;
    float rstd = rsqrtf(var + 1e-5f);

    const float* scl = g_ada + b * 1536 + (PASS == 0 ? 256 : 1024);
    const float* sft = g_ada + b * 1536 + (PASS == 0 ? 0   : 768);

    int ch = lane * 8;
    float o[8];
    #pragma unroll
    for (int j = 0; j < 8; j++) {
        float y = (e[j] - mean) * rstd * __ldg(&gamma[ch + j]) + __ldg(&beta[ch + j]);
        o[j] = y * (1.0f + scl[ch + j]) + sft[ch + j];
    }
    uint4 u;
    u.x = packbf(o[0], o[1]); u.y = packbf(o[2], o[3]);
    u.z = packbf(o[4], o[5]); u.w = packbf(o[6], o[7]);
    *(uint4*)(dst + ch) = u;
}

// ---------------------------------------------------------------------------
// Attention per (window, head): 64 threads, unnormalized softmax, float4 smem.
// ---------------------------------------------------------------------------
__global__ void attn_kernel(const float* __restrict__ rel_bias) {
    __shared__ float4 ks4[64][9];
    __shared__ float4 vs4[64][9];
    __shared__ float  sb[225];
    int widx = blockIdx.x;
    int h    = blockIdx.y;
    int n    = threadIdx.x;

    for (int i = n; i < 225; i += 64) sb[i] = __ldg(&rel_bias[i * 8 + h]);

    const bf16* rowp = g_qkvh + (size_t)widx * 64 * 768 + (size_t)n * 768 + h * 32;
    const float scale = 0.17677669529663687f;
    float q[32];
    #pragma unroll
    for (int j = 0; j < 4; j++) {
        uint4 uq = *(const uint4*)(rowp + j * 8);
        uint4 uk = *(const uint4*)(rowp + 256 + j * 8);
        uint4 uv = *(const uint4*)(rowp + 512 + j * 8);
        const uint32_t* pq = &uq.x;
        const uint32_t* pk = &uk.x;
        const uint32_t* pv = &uv.x;
        float kf[8], vf[8];
        #pragma unroll
        for (int p = 0; p < 4; p++) {
            float2 fq = __bfloat1622float2(*(const __nv_bfloat162*)&pq[p]);
            q[j * 8 + p * 2]     = fq.x * scale;
            q[j * 8 + p * 2 + 1] = fq.y * scale;
            float2 fk = __bfloat1622float2(*(const __nv_bfloat162*)&pk[p]);
            kf[p * 2] = fk.x; kf[p * 2 + 1] = fk.y;
            float2 fv = __bfloat1622float2(*(const __nv_bfloat162*)&pv[p]);
            vf[p * 2] = fv.x; vf[p * 2 + 1] = fv.y;
        }
        ks4[n][j * 2]     = make_float4(kf[0], kf[1], kf[2], kf[3]);
        ks4[n][j * 2 + 1] = make_float4(kf[4], kf[5], kf[6], kf[7]);
        vs4[n][j * 2]     = make_float4(vf[0], vf[1], vf[2], vf[3]);
        vs4[n][j * 2 + 1] = make_float4(vf[4], vf[5], vf[6], vf[7]);
    }
    __syncthreads();

    int wh = (widx >> 3) & 7, ww = widx & 7;
    int i1 = n >> 3, j1 = n & 7;
    int rv = wh * 8 + i1, cv = ww * 8 + j1;
    int idn = (rv < 56 ? 0 : (rv < 60 ? 1 : 2)) * 3 + (cv < 56 ? 0 : (cv < 60 ? 1 : 2));

    float o[32];
    #pragma unroll
    for (int d = 0; d < 32; d++) o[d] = 0.f;
    float sum = 0.f;

    for (int m = 0; m < 64; m++) {
        float s = 0.f;
        #pragma unroll
        for (int j = 0; j < 8; j++) {
            float4 kv = ks4[m][j];
            s = fmaf(q[j * 4 + 0], kv.x, s);
            s = fmaf(q[j * 4 + 1], kv.y, s);
            s = fmaf(q[j * 4 + 2], kv.z, s);
            s = fmaf(q[j * 4 + 3], kv.w, s);
        }
        int i2 = m >> 3, j2 = m & 7;
        s += sb[(i1 - i2 + 7) * 15 + (j1 - j2 + 7)];
        int rv2 = wh * 8 + i2, cv2 = ww * 8 + j2;
        int idm = (rv2 < 56 ? 0 : (rv2 < 60 ? 1 : 2)) * 3 +
                  (cv2 < 56 ? 0 : (cv2 < 60 ? 1 : 2));
        if (idm != idn) s -= 100.0f;
        float p = __expf(s);
        sum += p;
        #pragma unroll
        for (int j = 0; j < 8; j++) {
            float4 vv = vs4[m][j];
            o[j * 4 + 0] = fmaf(p, vv.x, o[j * 4 + 0]);
            o[j * 4 + 1] = fmaf(p, vv.y, o[j * 4 + 1]);
            o[j * 4 + 2] = fmaf(p, vv.z, o[j * 4 + 2]);
            o[j * 4 + 3] = fmaf(p, vv.w, o[j * 4 + 3]);
        }
    }
    float inv = 1.0f / sum;

    bf16* outp = g_attnh + (size_t)(widx * 64 + n) * 256 + h * 32;
    #pragma unroll
    for (int j = 0; j < 4; j++) {
        uint4 u;
        u.x = packbf(o[j*8+0]*inv, o[j*8+1]*inv);
        u.y = packbf(o[j*8+2]*inv, o[j*8+3]*inv);
        u.z = packbf(o[j*8+4]*inv, o[j*8+5]*inv);
        u.w = packbf(o[j*8+6]*inv, o[j*8+7]*inv);
        *(uint4*)(outp + j * 8) = u;
    }
}

// ---------------------------------------------------------------------------
// wmma bf16 GEMM: CTA 128x128, 4 warps (warp tile 64x64, 4x4 frags),
// BK=32, 4-stage cp.async pipeline, fused epilogue via smem roundtrip.
// MODE 0: g_qkvh     = bf16(A @ W + b)            N=768  K=256
// MODE 1: g_x1[perm] = x[perm] + gm*(A @ W + b)   N=256  K=256
// MODE 2: g_mlph     = bf16(gelu(A @ W + b))      N=1024 K=256
// MODE 3: out        = g_x1 + gp*(A @ W + b)      N=256  K=1024
// ---------------------------------------------------------------------------
#define AS_STR 40
#define BS_STR 136
#define STAGE_B (128 * AS_STR * 2 + 32 * BS_STR * 2)   // 10240 + 8704 = 18944
#define GEMM_SMEM (4 * STAGE_B)                         // 75776

template <int MODE>
__global__ __launch_bounds__(128)
void gemm_bf16(const float* __restrict__ bias,
               const float* __restrict__ xres,
               float* __restrict__ outp) {
    constexpr int K = (MODE == 3) ? 1024 : 256;
    constexpr int N = (MODE == 0) ? 768 : (MODE == 2) ? 1024 : 256;
    constexpr int NIT = K / 32;
    const bf16* A = (MODE == 0) ? g_hwinh : (MODE == 1) ? g_attnh
                  : (MODE == 2) ? g_h2h   : g_mlph;
    const bf16* W = g_wb + ((MODE == 0) ? WOFF_QKV : (MODE == 1) ? WOFF_PROJ
                         : (MODE == 2) ? WOFF_FC1 : WOFF_FC2);

    extern __shared__ char dsm[];
    int tid = threadIdx.x;
    int wid = tid >> 5;
    int wm = wid & 1;           // row block: wm*64
    int wn = wid >> 1;          // col block: wn*64
    int bm = blockIdx.y * 128, bn = blockIdx.x * 128;

    wmma::fragment<wmma::accumulator, 16, 16, 16, float> acc[4][4];
    #pragma unroll
    for (int mf = 0; mf < 4; mf++)
        #pragma unroll
        for (int nf = 0; nf < 4; nf++)
            wmma::fill_fragment(acc[mf][nf], 0.0f);

    const bf16* Abase = A + (size_t)bm * K;

    auto issue = [&](int it) {
        int buf = it & 3;
        bf16* As = (bf16*)(dsm + buf * STAGE_B);
        bf16* Bs = (bf16*)(dsm + buf * STAGE_B + 128 * AS_STR * 2);
        int k0 = it * 32;
        #pragma unroll
        for (int t = 0; t < 4; t++) {                    // A: 128x32, 512 chunks
            int idx = tid + t * 128;
            int r = idx >> 2, c = (idx & 3) * 8;
            __pipeline_memcpy_async(As + r * AS_STR + c,
                                    Abase + (size_t)r * K + k0 + c, 16);
        }
        #pragma unroll
        for (int t = 0; t < 4; t++) {                    // B: 32x128, 512 chunks
            int idx = tid + t * 128;
            int r = idx >> 4, c = (idx & 15) * 8;
            __pipeline_memcpy_async(Bs + r * BS_STR + c,
                                    W + (size_t)(k0 + r) * N + bn + c, 16);
        }
        __pipeline_commit();
    };

    issue(0);
    if (NIT > 1) issue(1);
    if (NIT > 2) issue(2);

    for (int it = 0; it < NIT; it++) {
        if (NIT - 1 - it >= 2)      __pipeline_wait_prior(2);
        else if (NIT - 1 - it == 1) __pipeline_wait_prior(1);
        else                        __pipeline_wait_prior(0);
        __syncthreads();

        const bf16* As = (const bf16*)(dsm + (it & 3) * STAGE_B);
        const bf16* Bs = (const bf16*)(dsm + (it & 3) * STAGE_B + 128 * AS_STR * 2);
        #pragma unroll
        for (int kk = 0; kk < 32; kk += 16) {
            wmma::fragment<wmma::matrix_a, 16, 16, 16, bf16, wmma::row_major> af[4];
            wmma::fragment<wmma::matrix_b, 16, 16, 16, bf16, wmma::row_major> bf[4];
            #pragma unroll
            for (int mf = 0; mf < 4; mf++)
                wmma::load_matrix_sync(af[mf], As + (wm * 64 + mf * 16) * AS_STR + kk, AS_STR);
            #pragma unroll
            for (int nf = 0; nf < 4; nf++)
                wmma::load_matrix_sync(bf[nf], Bs + kk * BS_STR + wn * 64 + nf * 16, BS_STR);
            #pragma unroll
            for (int mf = 0; mf < 4; mf++)
                #pragma unroll
                for (int nf = 0; nf < 4; nf++)
                    wmma::mma_sync(acc[mf][nf], af[mf], bf[nf], acc[mf][nf]);
        }
        if (it + 3 < NIT) issue(it + 3);
    }
    __syncthreads();

    // ---- epilogue via smem roundtrip (alias stage buffers: 64KB fp32) ----
    float* epi = (float*)dsm;
    #pragma unroll
    for (int mf = 0; mf < 4; mf++)
        #pragma unroll
        for (int nf = 0; nf < 4; nf++)
            wmma::store_matrix_sync(epi + (wm * 64 + mf * 16) * 128 + wn * 64 + nf * 16,
                                    acc[mf][nf], 128, wmma::mem_row_major);
    __syncthreads();

    #pragma unroll
    for (int t = 0; t < 16; t++) {
        int ch = tid + t * 128;           // 2048 chunks of 8 cols
        int r = ch >> 4;
        int c8 = (ch & 15) * 8;
        int col = bn + c8;
        int row = bm + r;
        float v[8];
        *(float4*)(v)     = *(const float4*)(epi + r * 128 + c8);
        *(float4*)(v + 4) = *(const float4*)(epi + r * 128 + c8 + 4);
        #pragma unroll
        for (int j = 0; j < 8; j++) v[j] += __ldg(&bias[col + j]);

        if (MODE == 0) {
            uint4 u;
            u.x = packbf(v[0], v[1]); u.y = packbf(v[2], v[3]);
            u.z = packbf(v[4], v[5]); u.w = packbf(v[6], v[7]);
            *(uint4*)(g_qkvh + (size_t)row * 768 + col) = u;
        } else if (MODE == 1) {
            int b = row >> 12, tt = row & 63, widx = (row >> 6) & 63;
            int wh = (widx >> 3) & 7, ww = widx & 7;
            int pr = (wh * 8 + (tt >> 3) + 4) & 63;
            int pc = (ww * 8 + (tt & 7) + 4) & 63;
            size_t prow = (size_t)(b * 4096 + pr * 64 + pc);
            const float* gm = g_ada + b * 1536 + 512;
            float o[8];
            #pragma unroll
            for (int j = 0; j < 8; j++)
                o[j] = __ldg(&xres[prow * 256 + col + j]) + gm[col + j] * v[j];
            *(float4*)(g_x1 + prow * 256 + col)     = *(float4*)(o);
            *(float4*)(g_x1 + prow * 256 + col + 4) = *(float4*)(o + 4);
        } else if (MODE == 2) {
            uint4 u;
            float o[8];
            #pragma unroll
            for (int j = 0; j < 8; j++)
                o[j] = 0.5f * v[j] * (1.0f + erff(v[j] * 0.70710678118654752f));
            u.x = packbf(o[0], o[1]); u.y = packbf(o[2], o[3]);
            u.z = packbf(o[4], o[5]); u.w = packbf(o[6], o[7]);
            *(uint4*)(g_mlph + (size_t)row * 1024 + col) = u;
        } else {
            int b = row >> 12;
            const float* gp = g_ada + b * 1536 + 1280;
            const float* x1 = g_x1 + (size_t)row * 256 + col;
            float o[8];
            #pragma unroll
            for (int j = 0; j < 8; j++)
                o[j] = x1[j] + gp[col + j] * v[j];
            *(float4*)(outp + (size_t)row * 256 + col)     = *(float4*)(o);
            *(float4*)(outp + (size_t)row * 256 + col + 4) = *(float4*)(o + 4);
        }
    }
}

// ---------------------------------------------------------------------------
extern "C" void kernel_launch(void* const* d_in, const int* in_sizes, int n_in,
                              void* d_out, int out_size) {
    const float* x       = (const float*)d_in[0];
    const float* cond    = (const float*)d_in[1];
    const float* norm1_g = (const float*)d_in[2];
    const float* norm1_b = (const float*)d_in[3];
    const float* w_qkv   = (const float*)d_in[4];
    const float* b_qkv   = (const float*)d_in[5];
    const float* rel_b   = (const float*)d_in[6];
    const float* w_proj  = (const float*)d_in[7];
    const float* b_proj  = (const float*)d_in[8];
    const float* norm2_g = (const float*)d_in[9];
    const float* norm2_b = (const float*)d_in[10];
    const float* w_fc1   = (const float*)d_in[11];
    const float* b_fc1   = (const float*)d_in[12];
    const float* w_fc2   = (const float*)d_in[13];
    const float* b_fc2   = (const float*)d_in[14];
    const float* w_ada   = (const float*)d_in[15];
    const float* b_ada   = (const float*)d_in[16];
    float* out = (float*)d_out;

    bf16* d_wb; cudaGetSymbolAddress((void**)&d_wb, g_wb);

    cudaFuncSetAttribute(gemm_bf16<0>, cudaFuncAttributeMaxDynamicSharedMemorySize, GEMM_SMEM);
    cudaFuncSetAttribute(gemm_bf16<1>, cudaFuncAttributeMaxDynamicSharedMemorySize, GEMM_SMEM);
    cudaFuncSetAttribute(gemm_bf16<2>, cudaFuncAttributeMaxDynamicSharedMemorySize, GEMM_SMEM);
    cudaFuncSetAttribute(gemm_bf16<3>, cudaFuncAttributeMaxDynamicSharedMemorySize, GEMM_SMEM);

    cvt_kernel<<<192, 256>>>(w_qkv,  d_wb + WOFF_QKV,  196608 / 4);
    cvt_kernel<<<64,  256>>>(w_proj, d_wb + WOFF_PROJ, 65536 / 4);
    cvt_kernel<<<256, 256>>>(w_fc1,  d_wb + WOFF_FC1,  262144 / 4);
    cvt_kernel<<<256, 256>>>(w_fc2,  d_wb + WOFF_FC2,  262144 / 4);
    ada_kernel<<<16, 256>>>(cond, w_ada, b_ada);
    ln_mod_kernel<0><<<8192, 256>>>(x, norm1_g, norm1_b);
    gemm_bf16<0><<<dim3(6, 512), 128, GEMM_SMEM>>>(b_qkv, nullptr, nullptr);
    attn_kernel<<<dim3(1024, 8), 64>>>(rel_b);
    gemm_bf16<1><<<dim3(2, 512), 128, GEMM_SMEM>>>(b_proj, x, nullptr);
    ln_mod_kernel<1><<<8192, 256>>>(nullptr, norm2_g, norm2_b);
    gemm_bf16<2><<<dim3(8, 512), 128, GEMM_SMEM>>>(b_fc1, nullptr, nullptr);
    gemm_bf16<3><<<dim3(2, 512), 128, GEMM_SMEM>>>(b_fc2, nullptr, out);
}